// round 9
// baseline (speedup 1.0000x reference)
#include <cuda_runtime.h>
#include <cuda_bf16.h>
#include <cstdint>
#include <math.h>

// MMDDistance on GB300 (sm_103 base target): split-bf16 3-pass HMMA gram,
// prepacked bf16(hi,lo), double-buffered cp.async pipeline, 2-launch graph.
//
//  k_prep : fp32 -> (hi,lo) bf16 prepack + row sq norms + column sums;
//           last-arriving block computes bandwidth (g_negc)
//  k_main : one 128x128 upper-triangle tile per CTA; 8 K-chunks of 32,
//           double-buffered cp.async staging overlapping 3-pass mma.sync;
//           epilogue: L2 -> one EX2 + 4 squarings -> signed partial;
//           last-arriving CTA does the deterministic final reduction.

#define NROWS 8192
#define NX    4096
#define DDIM  256
#define TB    128
#define NTILE 64
#define NWORK (NTILE * (NTILE + 1) / 2)   // 2080 upper-triangle tiles
#define CHUNK 32
#define NCHUNK (DDIM / CHUNK)              // 8
#define ROWB  64                           // smem row bytes (32 bf16)
#define TILEB (TB * ROWB)                  // 8192 B per tile
#define BUFB  (4 * TILEB)                  // 32768 B per pipeline stage

__device__ __nv_bfloat16 g_hi[NROWS * DDIM];
__device__ __nv_bfloat16 g_lo[NROWS * DDIM];
__device__ float  g_sq[NROWS];
__device__ double g_p_sqsum[256];
__device__ float  g_p_colf[256][DDIM];
__device__ float  g_negc;                  // -log2(e)/(16*bandwidth)
__device__ double g_partial[NWORK];
__device__ unsigned int g_done_prep;       // zero-init; self-resetting
__device__ unsigned int g_done_main;       // zero-init; self-resetting

// ---------------------------------------------------------------- helpers
__device__ __forceinline__ uint32_t smem_addr_u32(const void* p) {
    uint32_t a;
    asm("{ .reg .u64 t; cvta.to.shared.u64 t, %1; cvt.u32.u64 %0, t; }"
        : "=r"(a) : "l"(p));
    return a;
}
__device__ __forceinline__ void ldsm4(uint32_t addr, uint32_t r[4]) {
    asm volatile("ldmatrix.sync.aligned.m8n8.x4.shared.b16 {%0,%1,%2,%3}, [%4];"
                 : "=r"(r[0]), "=r"(r[1]), "=r"(r[2]), "=r"(r[3]) : "r"(addr));
}
__device__ __forceinline__ void mma16816(float d[4], const uint32_t a[4],
                                         uint32_t b0, uint32_t b1) {
    asm volatile(
        "mma.sync.aligned.m16n8k16.row.col.f32.bf16.bf16.f32 "
        "{%0,%1,%2,%3}, {%4,%5,%6,%7}, {%8,%9}, {%0,%1,%2,%3};"
        : "+f"(d[0]), "+f"(d[1]), "+f"(d[2]), "+f"(d[3])
        : "r"(a[0]), "r"(a[1]), "r"(a[2]), "r"(a[3]), "r"(b0), "r"(b1));
}
__device__ __forceinline__ void cpasync16(uint32_t dst, const void* src) {
    asm volatile("cp.async.ca.shared.global [%0], [%1], 16;"
                 :: "r"(dst), "l"(src) : "memory");
}
// 64B-row swizzle: 16B unit u (0..3) at row r -> u ^ ((q + (q>>2)) & 3), q=r&15.
// Conflict-free for 8-lane phases in both cp.async stores and ldmatrix reads.
__device__ __forceinline__ uint32_t swz_off(int r, int u) {
    int q = r & 15;
    int s = u ^ ((q + (q >> 2)) & 3);
    return (uint32_t)(r * ROWB + (s << 4));
}
__device__ __forceinline__ uint32_t lm_addr(uint32_t base, int row0, int k0,
                                            int lane) {
    int r = row0 + (lane & 15);
    int u = (k0 >> 3) + (lane >> 4);
    return base + swz_off(r, u);
}

// ---------------------------------------------------------------------------
// k_prep: 256 blocks x 256 thr; block b covers rows [32b, 32b+32).
// Prepack (hi,lo) bf16 + column partials + row sq; last block computes g_negc.
__global__ __launch_bounds__(256) void k_prep(const float* __restrict__ x,
                                              const float* __restrict__ y) {
    const int b = blockIdx.x, r0 = b * 32;
    const int w = threadIdx.x >> 5, lane = threadIdx.x & 31;
    __shared__ double ws[8];
    __shared__ double red[256];
    __shared__ int last_sh;

    const float* base = (r0 < NX) ? (x + (size_t)r0 * DDIM)
                                  : (y + (size_t)(r0 - NX) * DDIM);

    // conversion + column partials: thread owns column k over 32 rows
    {
        const int k = threadIdx.x;
        float acc = 0.f;
#pragma unroll 8
        for (int i = 0; i < 32; i++) {
            float v = base[(size_t)i * DDIM + k];
            __nv_bfloat16 h = __float2bfloat16_rn(v);
            float l = v - __bfloat162float(h);
            size_t idx = (size_t)(r0 + i) * DDIM + k;
            g_hi[idx] = h;
            g_lo[idx] = __float2bfloat16_rn(l);
            acc += v;
        }
        g_p_colf[b][k] = acc;
    }

    // row squared norms (reads are cache-hot)
    double wsum = 0.0;
#pragma unroll
    for (int rr = 0; rr < 4; rr++) {
        int r = w * 4 + rr;
        const float* p = base + (size_t)r * DDIM;
        float s = 0.f;
#pragma unroll
        for (int k = lane; k < DDIM; k += 32) { float v = p[k]; s = fmaf(v, v, s); }
#pragma unroll
        for (int off = 16; off; off >>= 1) s += __shfl_down_sync(0xffffffffu, s, off);
        if (lane == 0) { g_sq[r0 + r] = s; wsum += (double)s; }
    }
    if (lane == 0) ws[w] = wsum;
    __syncthreads();
    if (threadIdx.x == 0) {
        double t = 0.0;
#pragma unroll
        for (int i = 0; i < 8; i++) t += ws[i];
        g_p_sqsum[b] = t;
        __threadfence();
        last_sh = (atomicAdd(&g_done_prep, 1u) == 255u);
    }
    __syncthreads();

    if (!last_sh) return;
    // ---- last-arriving block: bandwidth ----
    __threadfence();
    const int t = threadIdx.x;
    float cs = 0.f;
#pragma unroll 8
    for (int bb = 0; bb < 256; bb++) cs += g_p_colf[bb][t];
    red[t] = (double)cs * (double)cs;
    __syncthreads();
    for (int off = 128; off; off >>= 1) {
        if (t < off) red[t] += red[t + off];
        __syncthreads();
    }
    double colsq = red[0];
    __syncthreads();
    red[t] = g_p_sqsum[t];
    __syncthreads();
    for (int off = 128; off; off >>= 1) {
        if (t < off) red[t] += red[t + off];
        __syncthreads();
    }
    if (t == 0) {
        double n = (double)NROWS;
        double sumL2 = 2.0 * n * red[0] - 2.0 * colsq;
        double bw = sumL2 / (n * n - n) / 4.0;   // / KERNEL_MUL^(KERNEL_NUM//2)
        g_negc = (float)(-M_LOG2E / (16.0 * bw));
        g_done_prep = 0;                          // reset for next replay
    }
}

// ---------------------------------------------------------------------------
// k_main: 2080 CTAs, one upper-triangle 128x128 tile each; 2-stage pipeline.
__global__ __launch_bounds__(256, 2) void k_main(float* __restrict__ out) {
    const int u = blockIdx.x;
    int bi = (int)((2.0f * NTILE + 1.0f
                    - sqrtf((2.0f * NTILE + 1.0f) * (2.0f * NTILE + 1.0f)
                            - 8.0f * (float)u)) * 0.5f);
    while (bi > 0 && bi * NTILE - bi * (bi - 1) / 2 > u) bi--;
    while ((bi + 1) * NTILE - (bi + 1) * bi / 2 <= u) bi++;
    const int bj = bi + (u - (bi * NTILE - bi * (bi - 1) / 2));

    extern __shared__ __align__(16) char dsm[];
    __shared__ float  sqA[TB], sqB[TB];
    __shared__ double red[256];
    __shared__ int last_sh;

    const int t    = threadIdx.x;
    const int lane = t & 31;
    const int w    = t >> 5;
    const int wr   = w & 3;          // warp row block  (32 rows)
    const int wc   = w >> 2;         // warp col block  (64 cols)

    const uint32_t sbase = smem_addr_u32(dsm);

    if (t < TB)      sqA[t]      = g_sq[bi * TB + t];
    else             sqB[t - TB] = g_sq[bj * TB + (t - TB)];

    const size_t rowA = (size_t)bi * TB * DDIM;
    const size_t rowB = (size_t)bj * TB * DDIM;
    const __nv_bfloat16* srcT[4] = {g_hi + rowA, g_lo + rowA,
                                    g_hi + rowB, g_lo + rowB};

    float acc[2][8][4];
#pragma unroll
    for (int m = 0; m < 2; m++)
#pragma unroll
        for (int n = 0; n < 8; n++)
#pragma unroll
            for (int q = 0; q < 4; q++) acc[m][n][q] = 0.f;

    // staging: thread handles segments t and t+256 of each tile
    // segment s -> row = s>>2, 16B-unit = s&3
    const int sr0 = t >> 2, su = t & 3;

#define STAGE(cc, buf)                                                        \
    do {                                                                      \
        const int kt_ = (cc) * CHUNK;                                         \
        const uint32_t bb_ = sbase + (uint32_t)(buf) * BUFB;                  \
        _Pragma("unroll")                                                     \
        for (int tl = 0; tl < 4; tl++) {                                      \
            _Pragma("unroll")                                                 \
            for (int i = 0; i < 2; i++) {                                     \
                int r = sr0 + i * 64;                                         \
                uint32_t dst = bb_ + (uint32_t)tl * TILEB + swz_off(r, su);   \
                cpasync16(dst, srcT[tl] + (size_t)r * DDIM + kt_ + su * 8);   \
            }                                                                 \
        }                                                                     \
        asm volatile("cp.async.commit_group;" ::: "memory");                  \
    } while (0)

    STAGE(0, 0);
    for (int c = 0; c < NCHUNK; c++) {
        if (c + 1 < NCHUNK) {
            STAGE(c + 1, (c + 1) & 1);
            asm volatile("cp.async.wait_group 1;" ::: "memory");
        } else {
            asm volatile("cp.async.wait_group 0;" ::: "memory");
        }
        __syncthreads();

        const uint32_t bb = sbase + (uint32_t)(c & 1) * BUFB;
        const uint32_t uAhi = bb, uAlo = bb + TILEB,
                       uBhi = bb + 2 * TILEB, uBlo = bb + 3 * TILEB;
#pragma unroll
        for (int ks = 0; ks < CHUNK / 16; ks++) {
            const int k0 = ks * 16;
            uint32_t ah[2][4], al[2][4];
#pragma unroll
            for (int m = 0; m < 2; m++) {
                int row0 = wr * 32 + m * 16;
                ldsm4(lm_addr(uAhi, row0, k0, lane), ah[m]);
                ldsm4(lm_addr(uAlo, row0, k0, lane), al[m]);
            }
#pragma unroll
            for (int h = 0; h < 2; h++) {
                uint32_t bh[2][4], bl[2][4];
#pragma unroll
                for (int s = 0; s < 2; s++) {
                    int n0 = wc * 64 + h * 32 + s * 16;
                    ldsm4(lm_addr(uBhi, n0, k0, lane), bh[s]);
                    ldsm4(lm_addr(uBlo, n0, k0, lane), bl[s]);
                }
#pragma unroll
                for (int m = 0; m < 2; m++)
#pragma unroll
                    for (int s = 0; s < 2; s++)
#pragma unroll
                        for (int sub = 0; sub < 2; sub++) {
                            const int nb = h * 4 + s * 2 + sub;
                            uint32_t b0 = bh[s][sub];       // k0-7
                            uint32_t b1 = bh[s][sub + 2];   // k8-15
                            mma16816(acc[m][nb], ah[m], b0, b1);  // hi*hi
                            b0 = bl[s][sub]; b1 = bl[s][sub + 2];
                            mma16816(acc[m][nb], ah[m], b0, b1);  // hi*lo
                            b0 = bh[s][sub]; b1 = bh[s][sub + 2];
                            mma16816(acc[m][nb], al[m], b0, b1);  // lo*hi
                        }
            }
        }
        __syncthreads();   // readers done before this buffer is restaged
    }

    // ---- epilogue: 5-kernel sum per pair ----
    const float negc = g_negc;
    const int g  = lane >> 2;
    const int c2 = (lane & 3) * 2;
    float fsum = 0.f;
#pragma unroll
    for (int m = 0; m < 2; m++) {
        const int r0 = wr * 32 + m * 16 + g;
        const float s0 = sqA[r0], s1 = sqA[r0 + 8];
#pragma unroll
        for (int nb = 0; nb < 8; nb++) {
            const int cc = wc * 64 + nb * 8 + c2;
            const float t0 = sqB[cc], t1 = sqB[cc + 1];
#pragma unroll
            for (int q = 0; q < 4; q++) {
                const float sr = (q >= 2) ? s1 : s0;
                const float sc = (q & 1) ? t1 : t0;
                float L2 = fmaxf(sr + sc - 2.f * acc[m][nb][q], 0.f);
                float v;
                asm("ex2.approx.ftz.f32 %0, %1;" : "=f"(v) : "f"(L2 * negc));
                float v2 = v * v, v4 = v2 * v2, v8 = v4 * v4, v16 = v8 * v8;
                fsum += v + v2 + v4 + v8 + v16;
            }
        }
    }
    double sgnw = ((bi < 32) == (bj < 32)) ? 1.0 : -1.0;
    if (bj != bi) sgnw *= 2.0;
    red[t] = (double)fsum * sgnw;
    __syncthreads();
    for (int off = 128; off; off >>= 1) {
        if (t < off) red[t] += red[t + off];
        __syncthreads();
    }
    if (t == 0) {
        g_partial[u] = red[0];
        __threadfence();
        last_sh = (atomicAdd(&g_done_main, 1u) == NWORK - 1);
    }
    __syncthreads();

    if (!last_sh) return;
    // ---- last-arriving CTA: deterministic final reduction ----
    __threadfence();
    double s = 0.0;
    for (int i = t; i < NWORK; i += 256) s += g_partial[i];
    red[t] = s;
    __syncthreads();
    for (int off = 128; off; off >>= 1) {
        if (t < off) red[t] += red[t + off];
        __syncthreads();
    }
    if (t == 0) {
        out[0] = (float)(red[0] / ((double)NX * (double)NX));
        g_done_main = 0;                          // reset for next replay
    }
}

// ---------------------------------------------------------------------------
#define SMEM_DYN (2 * BUFB)   // 65536 B -> 2 CTAs/SM

extern "C" void kernel_launch(void* const* d_in, const int* in_sizes, int n_in,
                              void* d_out, int out_size) {
    const float* x = (const float*)d_in[0];
    const float* y = (const float*)d_in[1];
    (void)in_sizes; (void)n_in; (void)out_size;

    k_prep<<<256, 256>>>(x, y);
    cudaFuncSetAttribute(k_main, cudaFuncAttributeMaxDynamicSharedMemorySize, SMEM_DYN);
    k_main<<<NWORK, 256, SMEM_DYN>>>((float*)d_out);
}

// round 10
// speedup vs baseline: 1.1009x; 1.1009x over previous
#include <cuda_runtime.h>
#include <cuda_bf16.h>
#include <cstdint>
#include <math.h>

// MMDDistance on GB300 (sm_103 base target): split-bf16 3-pass HMMA gram,
// prepacked bf16(hi,lo), cp.async staging, pass-major MMA scheduling.
//
//  k_prep : fp32 -> (hi,lo) bf16 prepack + row sq norms + column sums;
//           last-arriving block computes bandwidth (g_negc)
//  k_main : one 128x128 upper-triangle tile per CTA; 4 K-chunks of 64;
//           per k16: ldmatrix frags, then pass-major MMA (8 independent
//           accumulators between same-acc reuses); epilogue EX2 kernel sum;
//           last-arriving CTA does the deterministic final reduction.

#define NROWS 8192
#define NX    4096
#define DDIM  256
#define TB    128
#define NTILE 64
#define NWORK (NTILE * (NTILE + 1) / 2)   // 2080 upper-triangle tiles
#define CHUNK 64
#define NCHUNK (DDIM / CHUNK)              // 4
#define ROWB  128                          // smem row bytes (64 bf16, swizzled)
#define TILEB (TB * ROWB)                  // 16384 B per tile

__device__ __nv_bfloat16 g_hi[NROWS * DDIM];
__device__ __nv_bfloat16 g_lo[NROWS * DDIM];
__device__ float  g_sq[NROWS];
__device__ double g_p_sqsum[256];
__device__ float  g_p_colf[256][DDIM];
__device__ float  g_negc;                  // -log2(e)/(16*bandwidth)
__device__ double g_partial[NWORK];
__device__ unsigned int g_done_prep;       // zero-init; self-resetting
__device__ unsigned int g_done_main;       // zero-init; self-resetting

// ---------------------------------------------------------------- helpers
__device__ __forceinline__ uint32_t smem_addr_u32(const void* p) {
    uint32_t a;
    asm("{ .reg .u64 t; cvta.to.shared.u64 t, %1; cvt.u32.u64 %0, t; }"
        : "=r"(a) : "l"(p));
    return a;
}
__device__ __forceinline__ void ldsm4(uint32_t addr, uint32_t r[4]) {
    asm volatile("ldmatrix.sync.aligned.m8n8.x4.shared.b16 {%0,%1,%2,%3}, [%4];"
                 : "=r"(r[0]), "=r"(r[1]), "=r"(r[2]), "=r"(r[3]) : "r"(addr));
}
__device__ __forceinline__ void mma16816(float d[4], const uint32_t a[4],
                                         uint32_t b0, uint32_t b1) {
    asm volatile(
        "mma.sync.aligned.m16n8k16.row.col.f32.bf16.bf16.f32 "
        "{%0,%1,%2,%3}, {%4,%5,%6,%7}, {%8,%9}, {%0,%1,%2,%3};"
        : "+f"(d[0]), "+f"(d[1]), "+f"(d[2]), "+f"(d[3])
        : "r"(a[0]), "r"(a[1]), "r"(a[2]), "r"(a[3]), "r"(b0), "r"(b1));
}
__device__ __forceinline__ void cpasync16(uint32_t dst, const void* src) {
    asm volatile("cp.async.ca.shared.global [%0], [%1], 16;"
                 :: "r"(dst), "l"(src) : "memory");
}
// swizzled ldmatrix x4 address: logical (row, k) with k multiple of 8.
// smem layout: byte = row*128 + ((unit ^ (row & 7)) << 4), unit = k>>3.
__device__ __forceinline__ uint32_t lm_addr(uint32_t base, int row0, int k0,
                                            int lane) {
    int r = row0 + (lane & 15);
    int u = (k0 >> 3) + (lane >> 4);
    u ^= (r & 7);
    return base + (uint32_t)(r * ROWB + (u << 4));
}

// ---------------------------------------------------------------------------
// k_prep: 256 blocks x 256 thr; block b covers rows [32b, 32b+32).
__global__ __launch_bounds__(256) void k_prep(const float* __restrict__ x,
                                              const float* __restrict__ y) {
    const int b = blockIdx.x, r0 = b * 32;
    const int w = threadIdx.x >> 5, lane = threadIdx.x & 31;
    __shared__ double ws[8];
    __shared__ double red[256];
    __shared__ int last_sh;

    const float* base = (r0 < NX) ? (x + (size_t)r0 * DDIM)
                                  : (y + (size_t)(r0 - NX) * DDIM);

    // conversion + column partials: thread owns column k over 32 rows
    {
        const int k = threadIdx.x;
        float acc = 0.f;
#pragma unroll 8
        for (int i = 0; i < 32; i++) {
            float v = base[(size_t)i * DDIM + k];
            __nv_bfloat16 h = __float2bfloat16_rn(v);
            float l = v - __bfloat162float(h);
            size_t idx = (size_t)(r0 + i) * DDIM + k;
            g_hi[idx] = h;
            g_lo[idx] = __float2bfloat16_rn(l);
            acc += v;
        }
        g_p_colf[b][k] = acc;
    }

    // row squared norms (reads are cache-hot)
    double wsum = 0.0;
#pragma unroll
    for (int rr = 0; rr < 4; rr++) {
        int r = w * 4 + rr;
        const float* p = base + (size_t)r * DDIM;
        float s = 0.f;
#pragma unroll
        for (int k = lane; k < DDIM; k += 32) { float v = p[k]; s = fmaf(v, v, s); }
#pragma unroll
        for (int off = 16; off; off >>= 1) s += __shfl_down_sync(0xffffffffu, s, off);
        if (lane == 0) { g_sq[r0 + r] = s; wsum += (double)s; }
    }
    if (lane == 0) ws[w] = wsum;
    __syncthreads();
    if (threadIdx.x == 0) {
        double t = 0.0;
#pragma unroll
        for (int i = 0; i < 8; i++) t += ws[i];
        g_p_sqsum[b] = t;
        __threadfence();
        last_sh = (atomicAdd(&g_done_prep, 1u) == 255u);
    }
    __syncthreads();

    if (!last_sh) return;
    // ---- last-arriving block: bandwidth ----
    __threadfence();
    const int t = threadIdx.x;
    float cs = 0.f;
#pragma unroll 8
    for (int bb = 0; bb < 256; bb++) cs += g_p_colf[bb][t];
    red[t] = (double)cs * (double)cs;
    __syncthreads();
    for (int off = 128; off; off >>= 1) {
        if (t < off) red[t] += red[t + off];
        __syncthreads();
    }
    double colsq = red[0];
    __syncthreads();
    red[t] = g_p_sqsum[t];
    __syncthreads();
    for (int off = 128; off; off >>= 1) {
        if (t < off) red[t] += red[t + off];
        __syncthreads();
    }
    if (t == 0) {
        double n = (double)NROWS;
        double sumL2 = 2.0 * n * red[0] - 2.0 * colsq;
        double bw = sumL2 / (n * n - n) / 4.0;   // / KERNEL_MUL^(KERNEL_NUM//2)
        g_negc = (float)(-M_LOG2E / (16.0 * bw));
        g_done_prep = 0;                          // reset for next replay
    }
}

// ---------------------------------------------------------------------------
// k_main: 2080 CTAs, one upper-triangle 128x128 tile each.
__global__ __launch_bounds__(256, 2) void k_main(float* __restrict__ out) {
    const int u = blockIdx.x;
    int bi = (int)((2.0f * NTILE + 1.0f
                    - sqrtf((2.0f * NTILE + 1.0f) * (2.0f * NTILE + 1.0f)
                            - 8.0f * (float)u)) * 0.5f);
    while (bi > 0 && bi * NTILE - bi * (bi - 1) / 2 > u) bi--;
    while ((bi + 1) * NTILE - (bi + 1) * bi / 2 <= u) bi++;
    const int bj = bi + (u - (bi * NTILE - bi * (bi - 1) / 2));

    extern __shared__ __align__(16) char dsm[];
    __shared__ float  sqA[TB], sqB[TB];
    __shared__ double red[256];
    __shared__ int last_sh;

    const int t    = threadIdx.x;
    const int lane = t & 31;
    const int w    = t >> 5;
    const int wr   = w & 3;          // warp row block  (32 rows)
    const int wc   = w >> 2;         // warp col block  (64 cols)

    const uint32_t sbase = smem_addr_u32(dsm);
    const uint32_t uT[4] = {sbase, sbase + TILEB, sbase + 2 * TILEB,
                            sbase + 3 * TILEB};   // Ahi, Alo, Bhi, Blo

    if (t < TB)      sqA[t]      = g_sq[bi * TB + t];
    else             sqB[t - TB] = g_sq[bj * TB + (t - TB)];

    const size_t rowA = (size_t)bi * TB * DDIM;
    const size_t rowB = (size_t)bj * TB * DDIM;
    const __nv_bfloat16* srcT[4] = {g_hi + rowA, g_lo + rowA,
                                    g_hi + rowB, g_lo + rowB};

    float acc[2][8][4];
#pragma unroll
    for (int m = 0; m < 2; m++)
#pragma unroll
        for (int n = 0; n < 8; n++)
#pragma unroll
            for (int q = 0; q < 4; q++) acc[m][n][q] = 0.f;

    const int crow = t >> 3;   // 0..31: staging row base
    const int cun  = t & 7;    // 16B unit within 128B row

    for (int c = 0; c < NCHUNK; c++) {
        const int kt = c * CHUNK;
        __syncthreads();       // previous chunk's readers are done
#pragma unroll
        for (int tl = 0; tl < 4; tl++) {
            const __nv_bfloat16* src = srcT[tl] + kt + cun * 8;
#pragma unroll
            for (int i = 0; i < 4; i++) {
                int r = crow + i * 32;
                uint32_t dst = uT[tl] + (uint32_t)(r * ROWB
                             + ((cun ^ (r & 7)) << 4));
                cpasync16(dst, src + (size_t)r * DDIM);
            }
        }
        asm volatile("cp.async.commit_group;" ::: "memory");
        asm volatile("cp.async.wait_group 0;" ::: "memory");
        __syncthreads();

        // ---- MMA over this chunk: 4 k16 steps, pass-major scheduling ----
#pragma unroll
        for (int ks = 0; ks < CHUNK / 16; ks++) {
            const int k0 = ks * 16;
            uint32_t ah[2][4], al[2][4];
#pragma unroll
            for (int m = 0; m < 2; m++) {
                int row0 = wr * 32 + m * 16;
                ldsm4(lm_addr(uT[0], row0, k0, lane), ah[m]);
                ldsm4(lm_addr(uT[1], row0, k0, lane), al[m]);
            }
#pragma unroll
            for (int h = 0; h < 2; h++) {      // column halves of 32
                uint32_t bh[2][4], bl[2][4];
#pragma unroll
                for (int s = 0; s < 2; s++) {  // two n16 blocks
                    int n0 = wc * 64 + h * 32 + s * 16;
                    ldsm4(lm_addr(uT[2], n0, k0, lane), bh[s]);
                    ldsm4(lm_addr(uT[3], n0, k0, lane), bl[s]);
                }
                // pass-major: 8 independent accumulators per pass, so the
                // same-acc reuse distance is 8 MMA issues (covers RAW lat).
#pragma unroll
                for (int m = 0; m < 2; m++)    // pass 1: hi*hi
#pragma unroll
                    for (int s = 0; s < 2; s++)
#pragma unroll
                        for (int sub = 0; sub < 2; sub++)
                            mma16816(acc[m][h * 4 + s * 2 + sub], ah[m],
                                     bh[s][sub], bh[s][sub + 2]);
#pragma unroll
                for (int m = 0; m < 2; m++)    // pass 2: hi*lo
#pragma unroll
                    for (int s = 0; s < 2; s++)
#pragma unroll
                        for (int sub = 0; sub < 2; sub++)
                            mma16816(acc[m][h * 4 + s * 2 + sub], ah[m],
                                     bl[s][sub], bl[s][sub + 2]);
#pragma unroll
                for (int m = 0; m < 2; m++)    // pass 3: lo*hi
#pragma unroll
                    for (int s = 0; s < 2; s++)
#pragma unroll
                        for (int sub = 0; sub < 2; sub++)
                            mma16816(acc[m][h * 4 + s * 2 + sub], al[m],
                                     bh[s][sub], bh[s][sub + 2]);
            }
        }
    }

    // ---- epilogue: 5-kernel sum per pair ----
    const float negc = g_negc;
    const int g  = lane >> 2;
    const int c2 = (lane & 3) * 2;
    float fsum = 0.f;
#pragma unroll
    for (int m = 0; m < 2; m++) {
        const int r0 = wr * 32 + m * 16 + g;
        const float s0 = sqA[r0], s1 = sqA[r0 + 8];
#pragma unroll
        for (int nb = 0; nb < 8; nb++) {
            const int cc = wc * 64 + nb * 8 + c2;
            const float t0 = sqB[cc], t1 = sqB[cc + 1];
#pragma unroll
            for (int q = 0; q < 4; q++) {
                const float sr = (q >= 2) ? s1 : s0;
                const float sc = (q & 1) ? t1 : t0;
                float L2 = fmaxf(sr + sc - 2.f * acc[m][nb][q], 0.f);
                float v;
                asm("ex2.approx.ftz.f32 %0, %1;" : "=f"(v) : "f"(L2 * negc));
                float v2 = v * v, v4 = v2 * v2, v8 = v4 * v4, v16 = v8 * v8;
                fsum += v + v2 + v4 + v8 + v16;
            }
        }
    }
    double sgnw = ((bi < 32) == (bj < 32)) ? 1.0 : -1.0;
    if (bj != bi) sgnw *= 2.0;
    red[t] = (double)fsum * sgnw;
    __syncthreads();
    for (int off = 128; off; off >>= 1) {
        if (t < off) red[t] += red[t + off];
        __syncthreads();
    }
    if (t == 0) {
        g_partial[u] = red[0];
        __threadfence();
        last_sh = (atomicAdd(&g_done_main, 1u) == NWORK - 1);
    }
    __syncthreads();

    if (!last_sh) return;
    // ---- last-arriving CTA: deterministic final reduction ----
    __threadfence();
    double s = 0.0;
    for (int i = t; i < NWORK; i += 256) s += g_partial[i];
    red[t] = s;
    __syncthreads();
    for (int off = 128; off; off >>= 1) {
        if (t < off) red[t] += red[t + off];
        __syncthreads();
    }
    if (t == 0) {
        out[0] = (float)(red[0] / ((double)NX * (double)NX));
        g_done_main = 0;                          // reset for next replay
    }
}

// ---------------------------------------------------------------------------
#define SMEM_DYN (4 * TILEB)   // 65536 B -> 2 CTAs/SM

extern "C" void kernel_launch(void* const* d_in, const int* in_sizes, int n_in,
                              void* d_out, int out_size) {
    const float* x = (const float*)d_in[0];
    const float* y = (const float*)d_in[1];
    (void)in_sizes; (void)n_in; (void)out_size;

    k_prep<<<256, 256>>>(x, y);
    cudaFuncSetAttribute(k_main, cudaFuncAttributeMaxDynamicSharedMemorySize, SMEM_DYN);
    k_main<<<NWORK, 256, SMEM_DYN>>>((float*)d_out);
}